// round 13
// baseline (speedup 1.0000x reference)
#include <cuda_runtime.h>
#include <cuda_bf16.h>
#include <math.h>
#include <stdint.h>

#define DD 1024
#define HH 16
#define HDIM 64
#define TT 2048
#define BB 2
#define MR 4096            // B*T
#define THRESHF 0.29514f
#define SHARPF 15.0f

// ---------------- mma.sync / cp.async helpers (target-portable) -----------
__device__ __forceinline__ uint32_t s2u(const void* p) {
    uint32_t a;
    asm("{ .reg .u64 t; cvta.to.shared.u64 t, %1; cvt.u32.u64 %0, t; }" : "=r"(a) : "l"(p));
    return a;
}
#define SWZ(o) ((o) ^ (((o) >> 3) & 0x70))

__device__ __forceinline__ void ldsm4(uint32_t* r, uint32_t addr) {
    asm volatile("ldmatrix.sync.aligned.m8n8.x4.shared.b16 {%0,%1,%2,%3}, [%4];"
                 : "=r"(r[0]), "=r"(r[1]), "=r"(r[2]), "=r"(r[3]) : "r"(addr));
}
__device__ __forceinline__ void mma16816(float* d, const uint32_t* a, const uint32_t* b) {
    asm volatile("mma.sync.aligned.m16n8k16.row.col.f32.bf16.bf16.f32 "
                 "{%0,%1,%2,%3}, {%4,%5,%6,%7}, {%8,%9}, {%0,%1,%2,%3};"
                 : "+f"(d[0]), "+f"(d[1]), "+f"(d[2]), "+f"(d[3])
                 : "r"(a[0]), "r"(a[1]), "r"(a[2]), "r"(a[3]), "r"(b[0]), "r"(b[1]));
}
__device__ __forceinline__ void cpasync16(uint32_t dst, const void* src) {
    asm volatile("cp.async.cg.shared.global [%0], [%1], 16;" :: "r"(dst), "l"(src));
}
#define CP_COMMIT() asm volatile("cp.async.commit_group;" ::: "memory")
#define CP_WAIT1()  asm volatile("cp.async.wait_group 1;" ::: "memory")

__device__ __forceinline__ uint32_t packbf(float lo, float hi) {
    uint32_t d;
    asm("cvt.rn.bf16x2.f32 %0, %1, %2;" : "=r"(d) : "f"(hi), "f"(lo));
    return d;
}
__device__ __forceinline__ void split1(float v, __nv_bfloat16& h, __nv_bfloat16& l) {
    h = __float2bfloat16(v);
    l = __float2bfloat16(v - __bfloat162float(h));
}
__device__ __forceinline__ float sgm(float s) {
    float z = (s - THRESHF) * SHARPF;
    return __fdividef(1.0f, 1.0f + __expf(-z));
}

// -------------------- scratch (device globals; no allocation) --------------------
__device__ float g_q [(size_t)MR * DD];
__device__ float g_k [(size_t)MR * DD];
__device__ float g_v [(size_t)MR * DD];
__device__ float g_gq[MR * HH];   // layout [b][h][t]
__device__ float g_gk[MR * HH];   // layout [b][h][t]
__device__ __nv_bfloat16 g_xnhi[(size_t)MR * DD];
__device__ __nv_bfloat16 g_xnlo[(size_t)MR * DD];
__device__ __nv_bfloat16 g_xhi [(size_t)MR * DD];
__device__ __nv_bfloat16 g_xlo [(size_t)MR * DD];
__device__ __nv_bfloat16 g_chi [(size_t)MR * DD];
__device__ __nv_bfloat16 g_clo [(size_t)MR * DD];
__device__ __nv_bfloat16 g_qhi [(size_t)MR * DD];
__device__ __nv_bfloat16 g_qlo [(size_t)MR * DD];
__device__ __nv_bfloat16 g_khi [(size_t)MR * DD];
__device__ __nv_bfloat16 g_klo [(size_t)MR * DD];
__device__ __nv_bfloat16 g_vthi[(size_t)MR * DD];   // [b][h][d][t]
__device__ __nv_bfloat16 g_vtlo[(size_t)MR * DD];
__device__ __nv_bfloat16 g_wthi[(size_t)4 * DD * DD];   // [w][n][k]
__device__ __nv_bfloat16 g_wtlo[(size_t)4 * DD * DD];

// -------------------- LayerNorm: one block per row; emits bf16 hi/lo splits ----------
__global__ __launch_bounds__(256) void ln_kernel(const float* __restrict__ x,
                                                 const float* __restrict__ w,
                                                 const float* __restrict__ bia,
                                                 __nv_bfloat16* __restrict__ yhi,
                                                 __nv_bfloat16* __restrict__ ylo) {
    int row = blockIdx.x;
    const float4* xr = (const float4*)(x + (size_t)row * DD);
    float4 v = xr[threadIdx.x];
    float sum = v.x + v.y + v.z + v.w;
    float sq  = v.x*v.x + v.y*v.y + v.z*v.z + v.w*v.w;
#pragma unroll
    for (int o = 16; o > 0; o >>= 1) {
        sum += __shfl_xor_sync(0xffffffffu, sum, o);
        sq  += __shfl_xor_sync(0xffffffffu, sq, o);
    }
    __shared__ float s1[8], s2[8];
    int wid = threadIdx.x >> 5;
    if ((threadIdx.x & 31) == 0) { s1[wid] = sum; s2[wid] = sq; }
    __syncthreads();
    sum = 0.f; sq = 0.f;
#pragma unroll
    for (int i = 0; i < 8; i++) { sum += s1[i]; sq += s2[i]; }
    float mean = sum * (1.0f / DD);
    float var  = sq * (1.0f / DD) - mean * mean;
    float inv  = rsqrtf(var + 1e-5f);
    float4 wv = ((const float4*)w)[threadIdx.x];
    float4 bv = ((const float4*)bia)[threadIdx.x];
    float o[4];
    o[0] = (v.x - mean) * inv * wv.x + bv.x;
    o[1] = (v.y - mean) * inv * wv.y + bv.y;
    o[2] = (v.z - mean) * inv * wv.z + bv.z;
    o[3] = (v.w - mean) * inv * wv.w + bv.w;
    size_t idx = (size_t)row * DD + threadIdx.x * 4;
    __nv_bfloat16 h[4], l[4];
#pragma unroll
    for (int i = 0; i < 4; i++) split1(o[i], h[i], l[i]);
    *(__nv_bfloat162*)&yhi[idx]     = __nv_bfloat162(h[0], h[1]);
    *(__nv_bfloat162*)&yhi[idx + 2] = __nv_bfloat162(h[2], h[3]);
    *(__nv_bfloat162*)&ylo[idx]     = __nv_bfloat162(l[0], l[1]);
    *(__nv_bfloat162*)&ylo[idx + 2] = __nv_bfloat162(l[2], l[3]);
}

// -------------------- elementwise split: fp32 -> hi/lo bf16 --------------------
__global__ __launch_bounds__(256) void split_kernel(const float* __restrict__ in,
                                                    __nv_bfloat16* __restrict__ hi,
                                                    __nv_bfloat16* __restrict__ lo) {
    int i = blockIdx.x * 256 + threadIdx.x;
    float4 v = ((const float4*)in)[i];
    float o[4] = {v.x, v.y, v.z, v.w};
    __nv_bfloat16 h[4], l[4];
#pragma unroll
    for (int j = 0; j < 4; j++) split1(o[j], h[j], l[j]);
    size_t idx = (size_t)i * 4;
    *(__nv_bfloat162*)&hi[idx]     = __nv_bfloat162(h[0], h[1]);
    *(__nv_bfloat162*)&hi[idx + 2] = __nv_bfloat162(h[2], h[3]);
    *(__nv_bfloat162*)&lo[idx]     = __nv_bfloat162(l[0], l[1]);
    *(__nv_bfloat162*)&lo[idx + 2] = __nv_bfloat162(l[2], l[3]);
}

// ------------- weight transpose + split x4: W[k][n] -> Wt_hi/lo[w][n][k] -------------
__global__ void wtsplit4_kernel(const float* __restrict__ W0, const float* __restrict__ W1,
                                const float* __restrict__ W2, const float* __restrict__ W3,
                                __nv_bfloat16* __restrict__ Whi,
                                __nv_bfloat16* __restrict__ Wlo) {
    __shared__ float t[32][33];
    int wz = blockIdx.z;
    const float* W = wz == 0 ? W0 : wz == 1 ? W1 : wz == 2 ? W2 : W3;
    __nv_bfloat16* wh = Whi + (size_t)wz * DD * DD;
    __nv_bfloat16* wl = Wlo + (size_t)wz * DD * DD;
    int n0 = blockIdx.x * 32, k0 = blockIdx.y * 32;
    int tx = threadIdx.x, ty = threadIdx.y;   // (32, 8)
#pragma unroll
    for (int j = 0; j < 32; j += 8)
        t[ty + j][tx] = W[(size_t)(k0 + ty + j) * DD + n0 + tx];
    __syncthreads();
#pragma unroll
    for (int j = 0; j < 32; j += 8) {
        float v = t[tx][ty + j];
        __nv_bfloat16 h, l;
        split1(v, h, l);
        size_t o = (size_t)(n0 + ty + j) * DD + k0 + tx;
        wh[o] = h; wl[o] = l;
    }
}

// -------------------- per-head V transpose + split: v[b,t,h*64+d] -> vt[b,h,d,t] -----
__global__ void vtsplit_kernel(const float* __restrict__ v,
                               __nv_bfloat16* __restrict__ vthi,
                               __nv_bfloat16* __restrict__ vtlo) {
    __shared__ float t[32][33];
    int t0 = blockIdx.x * 32, d0 = blockIdx.y * 32, b = blockIdx.z;
    int tx = threadIdx.x, ty = threadIdx.y;   // (32, 8)
#pragma unroll
    for (int j = 0; j < 32; j += 8)
        t[ty + j][tx] = v[((size_t)b * TT + t0 + ty + j) * DD + d0 + tx];
    __syncthreads();
#pragma unroll
    for (int j = 0; j < 32; j += 8) {
        int hd = d0 + ty + j;
        float val = t[tx][ty + j];
        __nv_bfloat16 h, l;
        split1(val, h, l);
        size_t o = ((size_t)b * DD + hd) * TT + t0 + tx;
        vthi[o] = h; vtlo[o] = l;
    }
}

// ---------------- mma.sync GEMM with 3-stage cp.async pipeline -----------------
// C[M,N] = A[M,K] * Wt[N,K]^T  (split-bf16 x3). 128x128 tile, BK=64.
// Stage (65536 B): Ahi 0, Alo 16384, Bhi 32768, Blo 49152. 3 stages = 196608 B.
#define TG_STG 65536
#define TG_SMEM (3 * TG_STG)
__device__ __forceinline__ void tg_load_stage(
    uint32_t st, const __nv_bfloat16* Ahi, const __nv_bfloat16* Alo,
    const __nv_bfloat16* Bhi, const __nv_bfloat16* Blo,
    int m0, int n0, int k0, int tid) {
#pragma unroll
    for (int u = tid; u < 1024; u += 256) {
        int r = u >> 3, s = u & 7;
        uint32_t doff = SWZ((r << 7) + (s << 4));
        size_t ga = ((size_t)(m0 + r) << 10) + k0 + (s << 3);
        size_t gb = ((size_t)(n0 + r) << 10) + k0 + (s << 3);
        cpasync16(st + doff,         Ahi + ga);
        cpasync16(st + 16384 + doff, Alo + ga);
        cpasync16(st + 32768 + doff, Bhi + gb);
        cpasync16(st + 49152 + doff, Blo + gb);
    }
}
__global__ __launch_bounds__(256) void tgemm_kernel(
    const __nv_bfloat16* __restrict__ Ahi, const __nv_bfloat16* __restrict__ Alo,
    const __nv_bfloat16* __restrict__ Bhi, const __nv_bfloat16* __restrict__ Blo,
    const float* __restrict__ bias, float* __restrict__ C) {
    extern __shared__ char smem[];
    uint32_t sb = s2u(smem);
    int tid = threadIdx.x, wid = tid >> 5, lane = tid & 31;
    int m0 = blockIdx.y << 7, n0 = blockIdx.x << 7;
    int wm = (wid & 1) << 6;
    int wn = (wid >> 1) << 5;

    float acc[4][4][4] = {};

    int a_row = (lane & 15);
    int a_koff = (lane >> 4) << 4;
    int b_row = ((lane >> 4) << 3) + (lane & 7);
    int b_koff = ((lane >> 3) & 1) << 4;

    tg_load_stage(sb,          Ahi, Alo, Bhi, Blo, m0, n0, 0,  tid); CP_COMMIT();
    tg_load_stage(sb + TG_STG, Ahi, Alo, Bhi, Blo, m0, n0, 64, tid); CP_COMMIT();

    for (int kc = 0; kc < 16; kc++) {
        CP_WAIT1();            // stage kc complete (stage kc+1 may still be loading)
        __syncthreads();       // all threads done reading the buffer being refilled
        if (kc + 2 < 16)
            tg_load_stage(sb + ((kc + 2) % 3) * TG_STG, Ahi, Alo, Bhi, Blo,
                          m0, n0, (kc + 2) << 6, tid);
        CP_COMMIT();           // commit (possibly empty) to keep group count uniform
        uint32_t st = sb + (kc % 3) * TG_STG;

#pragma unroll
        for (int ks = 0; ks < 4; ks++) {
            int kb = ks << 5;
            uint32_t af[4][4];
            uint32_t bh[4][2], bl[4][2];
#pragma unroll
            for (int nt2 = 0; nt2 < 2; nt2++) {
                int nrow = wn + (nt2 << 4) + b_row;
                uint32_t off = SWZ((nrow << 7) + kb + b_koff);
                uint32_t r4[4];
                ldsm4(r4, st + 32768 + off);
                bh[nt2 * 2][0] = r4[0]; bh[nt2 * 2][1] = r4[1];
                bh[nt2 * 2 + 1][0] = r4[2]; bh[nt2 * 2 + 1][1] = r4[3];
                ldsm4(r4, st + 49152 + off);
                bl[nt2 * 2][0] = r4[0]; bl[nt2 * 2][1] = r4[1];
                bl[nt2 * 2 + 1][0] = r4[2]; bl[nt2 * 2 + 1][1] = r4[3];
            }
#pragma unroll
            for (int mt = 0; mt < 4; mt++) {
                int row = wm + (mt << 4) + a_row;
                ldsm4(af[mt], st + SWZ((row << 7) + kb + a_koff));
            }
#pragma unroll
            for (int mt = 0; mt < 4; mt++)
#pragma unroll
                for (int nt = 0; nt < 4; nt++) {
                    mma16816(acc[mt][nt], af[mt], bh[nt]);
                    mma16816(acc[mt][nt], af[mt], bl[nt]);
                }
#pragma unroll
            for (int mt = 0; mt < 4; mt++) {
                int row = wm + (mt << 4) + a_row;
                ldsm4(af[mt], st + 16384 + SWZ((row << 7) + kb + a_koff));
            }
#pragma unroll
            for (int mt = 0; mt < 4; mt++)
#pragma unroll
                for (int nt = 0; nt < 4; nt++)
                    mma16816(acc[mt][nt], af[mt], bh[nt]);
        }
    }

    int g = lane >> 2, t4 = lane & 3;
#pragma unroll
    for (int mt = 0; mt < 4; mt++) {
#pragma unroll
        for (int nt = 0; nt < 4; nt++) {
            int col = n0 + wn + (nt << 3) + (t4 << 1);
            float bx = 0.f, by = 0.f;
            if (bias) { float2 bv = *(const float2*)&bias[col]; bx = bv.x; by = bv.y; }
            int r0 = m0 + wm + (mt << 4) + g;
            *(float2*)&C[((size_t)r0 << 10) + col] =
                make_float2(acc[mt][nt][0] + bx, acc[mt][nt][1] + by);
            *(float2*)&C[((size_t)(r0 + 8) << 10) + col] =
                make_float2(acc[mt][nt][2] + bx, acc[mt][nt][3] + by);
        }
    }
}

// -------- L2 normalize q,k + gates (transposed [b,h,t]); warp per (b,t,h) --------
__global__ __launch_bounds__(256) void qknorm_kernel(const float* __restrict__ q,
                                                     const float* __restrict__ k,
                                                     const float* __restrict__ gqw,
                                                     const float* __restrict__ gkw,
                                                     __nv_bfloat16* __restrict__ qhi,
                                                     __nv_bfloat16* __restrict__ qlo,
                                                     __nv_bfloat16* __restrict__ khi,
                                                     __nv_bfloat16* __restrict__ klo,
                                                     float* __restrict__ gateq,
                                                     float* __restrict__ gatek) {
    int r = blockIdx.x * 8 + (threadIdx.x >> 5);   // (b*T+t)*H + h
    int lane = threadIdx.x & 31;
    int bt = r >> 4, h = r & 15;
    int b = bt >> 11, t = bt & 2047;
    size_t base = ((size_t)bt << 10) + (h << 6) + lane * 2;
    size_t gidx = (((size_t)(b << 4) + h) << 11) + t;

    float2 g1 = *(const float2*)&gqw[lane * 2];
    float2 g2 = *(const float2*)&gkw[lane * 2];

    float2 qv = *(const float2*)&q[base];
    float ss = qv.x * qv.x + qv.y * qv.y;
#pragma unroll
    for (int o = 16; o > 0; o >>= 1) ss += __shfl_xor_sync(0xffffffffu, ss, o);
    float inv = 1.0f / fmaxf(sqrtf(ss), 1e-12f);
    qv.x *= inv; qv.y *= inv;
    __nv_bfloat16 hx, lx, hy, ly;
    split1(qv.x, hx, lx); split1(qv.y, hy, ly);
    *(__nv_bfloat162*)&qhi[base] = __nv_bfloat162(hx, hy);
    *(__nv_bfloat162*)&qlo[base] = __nv_bfloat162(lx, ly);
    float gd = qv.x * g1.x + qv.y * g1.y;
#pragma unroll
    for (int o = 16; o > 0; o >>= 1) gd += __shfl_xor_sync(0xffffffffu, gd, o);
    if (lane == 0) gateq[gidx] = gd;

    float2 kv = *(const float2*)&k[base];
    ss = kv.x * kv.x + kv.y * kv.y;
#pragma unroll
    for (int o = 16; o > 0; o >>= 1) ss += __shfl_xor_sync(0xffffffffu, ss, o);
    inv = 1.0f / fmaxf(sqrtf(ss), 1e-12f);
    kv.x *= inv; kv.y *= inv;
    split1(kv.x, hx, lx); split1(kv.y, hy, ly);
    *(__nv_bfloat162*)&khi[base] = __nv_bfloat162(hx, hy);
    *(__nv_bfloat162*)&klo[base] = __nv_bfloat162(lx, ly);
    gd = kv.x * g2.x + kv.y * g2.y;
#pragma unroll
    for (int o = 16; o > 0; o >>= 1) gd += __shfl_xor_sync(0xffffffffu, gd, o);
    if (lane == 0) gatek[gidx] = gd;
}

// ------------- attention via mma.sync + 3-stage cp.async pipeline -------------
// Smem: Q hi 0, Q lo 16384; stages at 32768 + s*66048 (s=0..2)
//   (stage: Khi 0, Klo 16384, Vhi 32768, Vlo 49152, gk 65536..66047); gq at 230912.
#define AT_STG0 32768
#define AT_STGS 66048
#define AT_GQ   230912
#define A_SMEM  231424
__device__ __forceinline__ void at_load_stage(
    uint32_t st, const __nv_bfloat16* khi, const __nv_bfloat16* klo,
    const __nv_bfloat16* vthi, const __nv_bfloat16* vtlo,
    const float* gatek, size_t headoff, size_t vtoff, size_t gkoff,
    int s0, int tid) {
#pragma unroll
    for (int u = tid; u < 2048; u += 256) {   // K hi/lo
        int sp = u >> 10, r = (u >> 3) & 127, c = u & 7;
        const __nv_bfloat16* src = sp ? klo : khi;
        uint32_t dst = st + (sp ? 16384 : 0) + SWZ((r << 7) + (c << 4));
        cpasync16(dst, src + headoff + ((size_t)(s0 + r) << 10) + (c << 3));
    }
#pragma unroll
    for (int u = tid; u < 2048; u += 256) {   // V hi/lo (two 64-s halves)
        int sp = u >> 10, rem = u & 1023;
        int hf = rem >> 9, d = (rem >> 3) & 63, c = rem & 7;
        const __nv_bfloat16* src = sp ? vtlo : vthi;
        uint32_t dst = st + (sp ? 49152 : 32768) + (hf << 13) + SWZ((d << 7) + (c << 4));
        cpasync16(dst, src + vtoff + ((size_t)d << 11) + s0 + (hf << 6) + (c << 3));
    }
    if (tid < 32)
        cpasync16(st + 65536 + (tid << 4), gatek + gkoff + s0 + (tid << 2));
}
__global__ __launch_bounds__(256) void attn_kernel(
    const __nv_bfloat16* __restrict__ qhi, const __nv_bfloat16* __restrict__ qlo,
    const __nv_bfloat16* __restrict__ khi, const __nv_bfloat16* __restrict__ klo,
    const __nv_bfloat16* __restrict__ vthi, const __nv_bfloat16* __restrict__ vtlo,
    const float* __restrict__ gateq, const float* __restrict__ gatek,
    __nv_bfloat16* __restrict__ ohi, __nv_bfloat16* __restrict__ olo) {
    extern __shared__ char smem[];
    uint32_t sb = s2u(smem);
    int tid = threadIdx.x, wid = tid >> 5, lane = tid & 31;
    int g = lane >> 2, t4 = lane & 3;
    int t0 = blockIdx.x << 7;
    int h = blockIdx.y, b = blockIdx.z;
    size_t headoff = (size_t)b * TT * DD + (size_t)h * HDIM;
    size_t vtoff = ((size_t)b * DD + h * HDIM) * TT;
    size_t goff = ((size_t)(b * HH + h)) << 11;

    int a_row = lane & 15;
    int a_koff = (lane >> 4) << 4;
    int b_row = ((lane >> 4) << 3) + (lane & 7);
    int b_koff = ((lane >> 3) & 1) << 4;

    // Q tiles (regular loads) + gq + first two K/V stages (cp.async)
    for (int u = tid; u < 2048; u += 256) {
        int sp = u >> 10, r = (u >> 3) & 127, c = u & 7;
        const __nv_bfloat16* src = sp ? qlo : qhi;
        char* dst = smem + (sp ? 16384 : 0);
        *(uint4*)(dst + SWZ((r << 7) + (c << 4))) =
            *(const uint4*)(src + headoff + ((size_t)(t0 + r) << 10) + (c << 3));
    }
    if (tid < 32) {
        float4 gv = *(const float4*)&gateq[goff + t0 + (tid << 2)];
        *(float4*)(smem + AT_GQ + (tid << 4)) = gv;
    }
    at_load_stage(sb + AT_STG0, khi, klo, vthi, vtlo, gatek,
                  headoff, vtoff, goff, 0, tid);
    CP_COMMIT();
    at_load_stage(sb + AT_STG0 + AT_STGS, khi, klo, vthi, vtlo, gatek,
                  headoff, vtoff, goff, 128, tid);
    CP_COMMIT();
    __syncthreads();

    // resident Q fragments (16 t-rows per warp)
    int wm16 = wid << 4;
    uint32_t aQh[4][4], aQl[4][4];
#pragma unroll
    for (int ks = 0; ks < 4; ks++) {
        uint32_t off = SWZ(((wm16 + a_row) << 7) + (ks << 5) + a_koff);
        ldsm4(aQh[ks], sb + off);
        ldsm4(aQl[ks], sb + 16384 + off);
    }
    float gq0 = ((float*)(smem + AT_GQ))[wm16 + g];
    float gq1 = ((float*)(smem + AT_GQ))[wm16 + g + 8];

    float acc[8][4] = {};

    for (int it = 0; it < 16; it++) {
        CP_WAIT1();            // stage it ready
        __syncthreads();       // reads of recycled buffer finished
        if (it + 2 < 16)
            at_load_stage(sb + AT_STG0 + ((it + 2) % 3) * AT_STGS, khi, klo, vthi, vtlo,
                          gatek, headoff, vtoff, goff, (it + 2) << 7, tid);
        CP_COMMIT();
        uint32_t stoff = AT_STG0 + (it % 3) * AT_STGS;
        uint32_t st = sb + stoff;

        // S = Q K^T (3-term split)
        float sacc[16][4] = {};
#pragma unroll
        for (int ks = 0; ks < 4; ks++) {
            int kb = ks << 5;
#pragma unroll
            for (int nt2 = 0; nt2 < 8; nt2++) {
                uint32_t off = SWZ((((nt2 << 4) + b_row) << 7) + kb + b_koff);
                uint32_t kh[4], kl[4];
                ldsm4(kh, st + off);
                ldsm4(kl, st + 16384 + off);
                mma16816(sacc[nt2 * 2],     aQh[ks], kh);
                mma16816(sacc[nt2 * 2 + 1], aQh[ks], kh + 2);
                mma16816(sacc[nt2 * 2],     aQh[ks], kl);
                mma16816(sacc[nt2 * 2 + 1], aQh[ks], kl + 2);
                mma16816(sacc[nt2 * 2],     aQl[ks], kh);
                mma16816(sacc[nt2 * 2 + 1], aQl[ks], kh + 2);
            }
        }

        // P = sigmoid((S-th)*sharp)*gq*gk ; pack to bf16 hi/lo A-frags; PV mma
#pragma unroll
        for (int kp = 0; kp < 8; kp++) {
            int ntA = kp * 2, ntB = kp * 2 + 1;
            float2 gkA = *(const float2*)(smem + stoff + 65536 +
                                          (((ntA << 3) + (t4 << 1)) << 2));
            float2 gkB = *(const float2*)(smem + stoff + 65536 +
                                          (((ntB << 3) + (t4 << 1)) << 2));
            float pa0 = sgm(sacc[ntA][0]) * (gq0 * gkA.x);
            float pa1 = sgm(sacc[ntA][1]) * (gq0 * gkA.y);
            float pa2 = sgm(sacc[ntA][2]) * (gq1 * gkA.x);
            float pa3 = sgm(sacc[ntA][3]) * (gq1 * gkA.y);
            float pb0 = sgm(sacc[ntB][0]) * (gq0 * gkB.x);
            float pb1 = sgm(sacc[ntB][1]) * (gq0 * gkB.y);
            float pb2 = sgm(sacc[ntB][2]) * (gq1 * gkB.x);
            float pb3 = sgm(sacc[ntB][3]) * (gq1 * gkB.y);

            uint32_t ph[4], pl[4];
            ph[0] = packbf(pa0, pa1); ph[1] = packbf(pa2, pa3);
            ph[2] = packbf(pb0, pb1); ph[3] = packbf(pb2, pb3);
            {
                float r0 = pa0 - __uint_as_float(ph[0] << 16);
                float r1 = pa1 - __uint_as_float(ph[0] & 0xFFFF0000u);
                pl[0] = packbf(r0, r1);
                r0 = pa2 - __uint_as_float(ph[1] << 16);
                r1 = pa3 - __uint_as_float(ph[1] & 0xFFFF0000u);
                pl[1] = packbf(r0, r1);
                r0 = pb0 - __uint_as_float(ph[2] << 16);
                r1 = pb1 - __uint_as_float(ph[2] & 0xFFFF0000u);
                pl[2] = packbf(r0, r1);
                r0 = pb2 - __uint_as_float(ph[3] << 16);
                r1 = pb3 - __uint_as_float(ph[3] & 0xFFFF0000u);
                pl[3] = packbf(r0, r1);
            }

#pragma unroll
            for (int nt2 = 0; nt2 < 4; nt2++) {
                uint32_t so = SWZ((((nt2 << 4) + b_row) << 7) + ((kp & 3) << 5) + b_koff)
                              + ((kp >> 2) << 13);
                uint32_t vh[4], vl[4];
                ldsm4(vh, st + 32768 + so);
                ldsm4(vl, st + 49152 + so);
                mma16816(acc[nt2 * 2],     ph, vh);
                mma16816(acc[nt2 * 2 + 1], ph, vh + 2);
                mma16816(acc[nt2 * 2],     ph, vl);
                mma16816(acc[nt2 * 2 + 1], ph, vl + 2);
                mma16816(acc[nt2 * 2],     pl, vh);
                mma16816(acc[nt2 * 2 + 1], pl, vh + 2);
            }
        }
    }

    // epilogue: collapse -> bf16 hi/lo splits
#pragma unroll
    for (int nt = 0; nt < 8; nt++) {
        int d0 = (nt << 3) + (t4 << 1);
        int r0 = t0 + wm16 + g;
        __nv_bfloat16 h0, l0, h1, l1;
        split1(acc[nt][0], h0, l0); split1(acc[nt][1], h1, l1);
        size_t i0 = headoff + ((size_t)r0 << 10) + d0;
        *(__nv_bfloat162*)&ohi[i0] = __nv_bfloat162(h0, h1);
        *(__nv_bfloat162*)&olo[i0] = __nv_bfloat162(l0, l1);
        split1(acc[nt][2], h0, l0); split1(acc[nt][3], h1, l1);
        size_t i1 = headoff + ((size_t)(r0 + 8) << 10) + d0;
        *(__nv_bfloat162*)&ohi[i1] = __nv_bfloat162(h0, h1);
        *(__nv_bfloat162*)&olo[i1] = __nv_bfloat162(l0, l1);
    }
}

// -------------------- launch --------------------
extern "C" void kernel_launch(void* const* d_in, const int* in_sizes, int n_in,
                              void* d_out, int out_size) {
    (void)in_sizes; (void)n_in; (void)out_size;
    const float* x   = (const float*)d_in[0];
    const float* Wq  = (const float*)d_in[1];
    const float* Wk  = (const float*)d_in[2];
    const float* Wv  = (const float*)d_in[3];
    const float* gq  = (const float*)d_in[4];
    const float* gk  = (const float*)d_in[5];
    const float* Wo  = (const float*)d_in[6];
    const float* bo  = (const float*)d_in[7];
    const float* lnw = (const float*)d_in[8];
    const float* lnb = (const float*)d_in[9];
    float* out = (float*)d_out;

    float *qb, *kb, *vb, *gqv, *gkv;
    __nv_bfloat16 *xnhi, *xnlo, *xhi, *xlo, *chi, *clo, *wthi, *wtlo;
    __nv_bfloat16 *qhi, *qlo, *khi, *klo, *vthi, *vtlo;
    cudaGetSymbolAddress((void**)&qb,   g_q);
    cudaGetSymbolAddress((void**)&kb,   g_k);
    cudaGetSymbolAddress((void**)&vb,   g_v);
    cudaGetSymbolAddress((void**)&gqv,  g_gq);
    cudaGetSymbolAddress((void**)&gkv,  g_gk);
    cudaGetSymbolAddress((void**)&xnhi, g_xnhi);
    cudaGetSymbolAddress((void**)&xnlo, g_xnlo);
    cudaGetSymbolAddress((void**)&xhi,  g_xhi);
    cudaGetSymbolAddress((void**)&xlo,  g_xlo);
    cudaGetSymbolAddress((void**)&chi,  g_chi);
    cudaGetSymbolAddress((void**)&clo,  g_clo);
    cudaGetSymbolAddress((void**)&qhi,  g_qhi);
    cudaGetSymbolAddress((void**)&qlo,  g_qlo);
    cudaGetSymbolAddress((void**)&khi,  g_khi);
    cudaGetSymbolAddress((void**)&klo,  g_klo);
    cudaGetSymbolAddress((void**)&vthi, g_vthi);
    cudaGetSymbolAddress((void**)&vtlo, g_vtlo);
    cudaGetSymbolAddress((void**)&wthi, g_wthi);
    cudaGetSymbolAddress((void**)&wtlo, g_wtlo);

    const size_t WSZ = (size_t)DD * DD;

    cudaFuncSetAttribute(attn_kernel, cudaFuncAttributeMaxDynamicSharedMemorySize,
                         A_SMEM);
    cudaFuncSetAttribute(tgemm_kernel, cudaFuncAttributeMaxDynamicSharedMemorySize,
                         TG_SMEM);

    dim3 tgrid(DD / 128, MR / 128);       // (8, 32)
    dim3 wtgrid(DD / 32, DD / 32, 4);
    dim3 wtblk(32, 8);
    dim3 vtgrid(TT / 32, DD / 32, BB);

    // prep
    ln_kernel<<<MR, 256>>>(x, lnw, lnb, xnhi, xnlo);
    split_kernel<<<(MR * DD) / (256 * 4), 256>>>(x, xhi, xlo);
    wtsplit4_kernel<<<wtgrid, wtblk>>>(Wq, Wk, Wv, Wo, wthi, wtlo);

    // projections on tensor cores
    tgemm_kernel<<<tgrid, 256, TG_SMEM>>>(xnhi, xnlo, wthi + 0 * WSZ, wtlo + 0 * WSZ,
                                          nullptr, qb);
    tgemm_kernel<<<tgrid, 256, TG_SMEM>>>(xnhi, xnlo, wthi + 1 * WSZ, wtlo + 1 * WSZ,
                                          nullptr, kb);
    tgemm_kernel<<<tgrid, 256, TG_SMEM>>>(xhi,  xlo,  wthi + 2 * WSZ, wtlo + 2 * WSZ,
                                          nullptr, vb);

    qknorm_kernel<<<(MR * HH) / 8, 256>>>(qb, kb, gq, gk, qhi, qlo, khi, klo, gqv, gkv);
    vtsplit_kernel<<<vtgrid, wtblk>>>(vb, vthi, vtlo);

    attn_kernel<<<dim3(TT / 128, HH, BB), 256, A_SMEM>>>(
        qhi, qlo, khi, klo, vthi, vtlo, gqv, gkv, chi, clo);

    // output projection + bias
    tgemm_kernel<<<tgrid, 256, TG_SMEM>>>(chi, clo, wthi + 3 * WSZ, wtlo + 3 * WSZ,
                                          bo, out);
}

// round 14
// speedup vs baseline: 1.0294x; 1.0294x over previous
#include <cuda_runtime.h>
#include <cuda_bf16.h>
#include <math.h>
#include <stdint.h>

#define DD 1024
#define HH 16
#define HDIM 64
#define TT 2048
#define BB 2
#define MR 4096            // B*T
#define THRESHF 0.29514f
#define SHARPF 15.0f

// ---------------- mma.sync / cp.async helpers (target-portable) -----------
__device__ __forceinline__ uint32_t s2u(const void* p) {
    uint32_t a;
    asm("{ .reg .u64 t; cvta.to.shared.u64 t, %1; cvt.u32.u64 %0, t; }" : "=r"(a) : "l"(p));
    return a;
}
#define SWZ(o) ((o) ^ (((o) >> 3) & 0x70))

__device__ __forceinline__ void ldsm4(uint32_t* r, uint32_t addr) {
    asm volatile("ldmatrix.sync.aligned.m8n8.x4.shared.b16 {%0,%1,%2,%3}, [%4];"
                 : "=r"(r[0]), "=r"(r[1]), "=r"(r[2]), "=r"(r[3]) : "r"(addr));
}
__device__ __forceinline__ void mma16816(float* d, const uint32_t* a, const uint32_t* b) {
    asm volatile("mma.sync.aligned.m16n8k16.row.col.f32.bf16.bf16.f32 "
                 "{%0,%1,%2,%3}, {%4,%5,%6,%7}, {%8,%9}, {%0,%1,%2,%3};"
                 : "+f"(d[0]), "+f"(d[1]), "+f"(d[2]), "+f"(d[3])
                 : "r"(a[0]), "r"(a[1]), "r"(a[2]), "r"(a[3]), "r"(b[0]), "r"(b[1]));
}
__device__ __forceinline__ void cpasync16(uint32_t dst, const void* src) {
    asm volatile("cp.async.cg.shared.global [%0], [%1], 16;" :: "r"(dst), "l"(src));
}
#define CP_COMMIT() asm volatile("cp.async.commit_group;" ::: "memory")
#define CP_WAIT1()  asm volatile("cp.async.wait_group 1;" ::: "memory")
#define CP_WAIT0()  asm volatile("cp.async.wait_group 0;" ::: "memory")

__device__ __forceinline__ uint32_t packbf(float lo, float hi) {
    uint32_t d;
    asm("cvt.rn.bf16x2.f32 %0, %1, %2;" : "=r"(d) : "f"(hi), "f"(lo));
    return d;
}
__device__ __forceinline__ void split1(float v, __nv_bfloat16& h, __nv_bfloat16& l) {
    h = __float2bfloat16(v);
    l = __float2bfloat16(v - __bfloat162float(h));
}
__device__ __forceinline__ float sgm(float s) {
    float z = (s - THRESHF) * SHARPF;
    return __fdividef(1.0f, 1.0f + __expf(-z));
}

// -------------------- scratch (device globals; no allocation) --------------------
__device__ float g_q [(size_t)MR * DD];
__device__ float g_k [(size_t)MR * DD];
__device__ float g_v [(size_t)MR * DD];
__device__ float g_gq[MR * HH];   // layout [b][h][t]
__device__ float g_gk[MR * HH];   // layout [b][h][t]
__device__ __nv_bfloat16 g_xnhi[(size_t)MR * DD];
__device__ __nv_bfloat16 g_xnlo[(size_t)MR * DD];
__device__ __nv_bfloat16 g_xhi [(size_t)MR * DD];
__device__ __nv_bfloat16 g_xlo [(size_t)MR * DD];
__device__ __nv_bfloat16 g_chi [(size_t)MR * DD];
__device__ __nv_bfloat16 g_clo [(size_t)MR * DD];
__device__ __nv_bfloat16 g_qhi [(size_t)MR * DD];
__device__ __nv_bfloat16 g_qlo [(size_t)MR * DD];
__device__ __nv_bfloat16 g_khi [(size_t)MR * DD];
__device__ __nv_bfloat16 g_klo [(size_t)MR * DD];
__device__ __nv_bfloat16 g_vthi[(size_t)MR * DD];   // [b][h][d][t]
__device__ __nv_bfloat16 g_vtlo[(size_t)MR * DD];
__device__ __nv_bfloat16 g_wthi[(size_t)4 * DD * DD];   // [w][n][k]
__device__ __nv_bfloat16 g_wtlo[(size_t)4 * DD * DD];

// -------------------- LayerNorm: one block per row; emits bf16 hi/lo splits ----------
__global__ __launch_bounds__(256) void ln_kernel(const float* __restrict__ x,
                                                 const float* __restrict__ w,
                                                 const float* __restrict__ bia,
                                                 __nv_bfloat16* __restrict__ yhi,
                                                 __nv_bfloat16* __restrict__ ylo) {
    int row = blockIdx.x;
    const float4* xr = (const float4*)(x + (size_t)row * DD);
    float4 v = xr[threadIdx.x];
    float sum = v.x + v.y + v.z + v.w;
    float sq  = v.x*v.x + v.y*v.y + v.z*v.z + v.w*v.w;
#pragma unroll
    for (int o = 16; o > 0; o >>= 1) {
        sum += __shfl_xor_sync(0xffffffffu, sum, o);
        sq  += __shfl_xor_sync(0xffffffffu, sq, o);
    }
    __shared__ float s1[8], s2[8];
    int wid = threadIdx.x >> 5;
    if ((threadIdx.x & 31) == 0) { s1[wid] = sum; s2[wid] = sq; }
    __syncthreads();
    sum = 0.f; sq = 0.f;
#pragma unroll
    for (int i = 0; i < 8; i++) { sum += s1[i]; sq += s2[i]; }
    float mean = sum * (1.0f / DD);
    float var  = sq * (1.0f / DD) - mean * mean;
    float inv  = rsqrtf(var + 1e-5f);
    float4 wv = ((const float4*)w)[threadIdx.x];
    float4 bv = ((const float4*)bia)[threadIdx.x];
    float o[4];
    o[0] = (v.x - mean) * inv * wv.x + bv.x;
    o[1] = (v.y - mean) * inv * wv.y + bv.y;
    o[2] = (v.z - mean) * inv * wv.z + bv.z;
    o[3] = (v.w - mean) * inv * wv.w + bv.w;
    size_t idx = (size_t)row * DD + threadIdx.x * 4;
    __nv_bfloat16 h[4], l[4];
#pragma unroll
    for (int i = 0; i < 4; i++) split1(o[i], h[i], l[i]);
    *(__nv_bfloat162*)&yhi[idx]     = __nv_bfloat162(h[0], h[1]);
    *(__nv_bfloat162*)&yhi[idx + 2] = __nv_bfloat162(h[2], h[3]);
    *(__nv_bfloat162*)&ylo[idx]     = __nv_bfloat162(l[0], l[1]);
    *(__nv_bfloat162*)&ylo[idx + 2] = __nv_bfloat162(l[2], l[3]);
}

// -------------------- elementwise split: fp32 -> hi/lo bf16 --------------------
__global__ __launch_bounds__(256) void split_kernel(const float* __restrict__ in,
                                                    __nv_bfloat16* __restrict__ hi,
                                                    __nv_bfloat16* __restrict__ lo) {
    int i = blockIdx.x * 256 + threadIdx.x;
    float4 v = ((const float4*)in)[i];
    float o[4] = {v.x, v.y, v.z, v.w};
    __nv_bfloat16 h[4], l[4];
#pragma unroll
    for (int j = 0; j < 4; j++) split1(o[j], h[j], l[j]);
    size_t idx = (size_t)i * 4;
    *(__nv_bfloat162*)&hi[idx]     = __nv_bfloat162(h[0], h[1]);
    *(__nv_bfloat162*)&hi[idx + 2] = __nv_bfloat162(h[2], h[3]);
    *(__nv_bfloat162*)&lo[idx]     = __nv_bfloat162(l[0], l[1]);
    *(__nv_bfloat162*)&lo[idx + 2] = __nv_bfloat162(l[2], l[3]);
}

// ------------- weight transpose + split x4: W[k][n] -> Wt_hi/lo[w][n][k] -------------
__global__ void wtsplit4_kernel(const float* __restrict__ W0, const float* __restrict__ W1,
                                const float* __restrict__ W2, const float* __restrict__ W3,
                                __nv_bfloat16* __restrict__ Whi,
                                __nv_bfloat16* __restrict__ Wlo) {
    __shared__ float t[32][33];
    int wz = blockIdx.z;
    const float* W = wz == 0 ? W0 : wz == 1 ? W1 : wz == 2 ? W2 : W3;
    __nv_bfloat16* wh = Whi + (size_t)wz * DD * DD;
    __nv_bfloat16* wl = Wlo + (size_t)wz * DD * DD;
    int n0 = blockIdx.x * 32, k0 = blockIdx.y * 32;
    int tx = threadIdx.x, ty = threadIdx.y;   // (32, 8)
#pragma unroll
    for (int j = 0; j < 32; j += 8)
        t[ty + j][tx] = W[(size_t)(k0 + ty + j) * DD + n0 + tx];
    __syncthreads();
#pragma unroll
    for (int j = 0; j < 32; j += 8) {
        float v = t[tx][ty + j];
        __nv_bfloat16 h, l;
        split1(v, h, l);
        size_t o = (size_t)(n0 + ty + j) * DD + k0 + tx;
        wh[o] = h; wl[o] = l;
    }
}

// -------------------- per-head V transpose + split: v[b,t,h*64+d] -> vt[b,h,d,t] -----
__global__ void vtsplit_kernel(const float* __restrict__ v,
                               __nv_bfloat16* __restrict__ vthi,
                               __nv_bfloat16* __restrict__ vtlo) {
    __shared__ float t[32][33];
    int t0 = blockIdx.x * 32, d0 = blockIdx.y * 32, b = blockIdx.z;
    int tx = threadIdx.x, ty = threadIdx.y;   // (32, 8)
#pragma unroll
    for (int j = 0; j < 32; j += 8)
        t[ty + j][tx] = v[((size_t)b * TT + t0 + ty + j) * DD + d0 + tx];
    __syncthreads();
#pragma unroll
    for (int j = 0; j < 32; j += 8) {
        int hd = d0 + ty + j;
        float val = t[tx][ty + j];
        __nv_bfloat16 h, l;
        split1(val, h, l);
        size_t o = ((size_t)b * DD + hd) * TT + t0 + tx;
        vthi[o] = h; vtlo[o] = l;
    }
}

// -------- mma.sync GEMM, 64x128 tile, 2-stage cp.async, 2 CTAs/SM ---------
// C[M,N] = A[M,K] * Wt[N,K]^T  (split-bf16 x3). BK=64.
// Stage (49152 B): Ahi 0, Alo 8192, Bhi 16384, Blo 32768.
#define TG_STG 49152
#define TG_SMEM (2 * TG_STG)    // 98304 -> 2 CTAs/SM
__device__ __forceinline__ void tg_load_stage(
    uint32_t st, const __nv_bfloat16* Ahi, const __nv_bfloat16* Alo,
    const __nv_bfloat16* Bhi, const __nv_bfloat16* Blo,
    int m0, int n0, int k0, int tid) {
#pragma unroll
    for (int u = tid; u < 512; u += 256) {      // A hi/lo: 64 rows
        int r = u >> 3, s = u & 7;
        uint32_t doff = SWZ((r << 7) + (s << 4));
        size_t ga = ((size_t)(m0 + r) << 10) + k0 + (s << 3);
        cpasync16(st + doff,        Ahi + ga);
        cpasync16(st + 8192 + doff, Alo + ga);
    }
#pragma unroll
    for (int u = tid; u < 1024; u += 256) {     // B hi/lo: 128 rows
        int r = u >> 3, s = u & 7;
        uint32_t doff = SWZ((r << 7) + (s << 4));
        size_t gb = ((size_t)(n0 + r) << 10) + k0 + (s << 3);
        cpasync16(st + 16384 + doff, Bhi + gb);
        cpasync16(st + 32768 + doff, Blo + gb);
    }
}
__global__ __launch_bounds__(256) void tgemm_kernel(
    const __nv_bfloat16* __restrict__ Ahi, const __nv_bfloat16* __restrict__ Alo,
    const __nv_bfloat16* __restrict__ Bhi, const __nv_bfloat16* __restrict__ Blo,
    const float* __restrict__ bias, float* __restrict__ C) {
    extern __shared__ char smem[];
    uint32_t sb = s2u(smem);
    int tid = threadIdx.x, wid = tid >> 5, lane = tid & 31;
    int m0 = blockIdx.y << 6, n0 = blockIdx.x << 7;
    int wm = (wid & 1) << 5;      // 0 or 32
    int wn = (wid >> 1) << 5;     // 0,32,64,96

    float acc[2][4][4] = {};

    int a_row = (lane & 15);
    int a_koff = (lane >> 4) << 4;
    int b_row = ((lane >> 4) << 3) + (lane & 7);
    int b_koff = ((lane >> 3) & 1) << 4;

    tg_load_stage(sb, Ahi, Alo, Bhi, Blo, m0, n0, 0, tid);
    CP_COMMIT();

    for (int kc = 0; kc < 16; kc++) {
        if (kc < 15) {
            tg_load_stage(sb + ((kc + 1) & 1) * TG_STG, Ahi, Alo, Bhi, Blo,
                          m0, n0, (kc + 1) << 6, tid);
            CP_COMMIT();
            CP_WAIT1();
        } else {
            CP_WAIT0();
        }
        __syncthreads();
        uint32_t st = sb + (kc & 1) * TG_STG;

#pragma unroll
        for (int ks = 0; ks < 4; ks++) {
            int kb = ks << 5;
            uint32_t af[2][4];
            uint32_t bh[4][2], bl[4][2];
#pragma unroll
            for (int nt2 = 0; nt2 < 2; nt2++) {
                int nrow = wn + (nt2 << 4) + b_row;
                uint32_t off = SWZ((nrow << 7) + kb + b_koff);
                uint32_t r4[4];
                ldsm4(r4, st + 16384 + off);
                bh[nt2 * 2][0] = r4[0]; bh[nt2 * 2][1] = r4[1];
                bh[nt2 * 2 + 1][0] = r4[2]; bh[nt2 * 2 + 1][1] = r4[3];
                ldsm4(r4, st + 32768 + off);
                bl[nt2 * 2][0] = r4[0]; bl[nt2 * 2][1] = r4[1];
                bl[nt2 * 2 + 1][0] = r4[2]; bl[nt2 * 2 + 1][1] = r4[3];
            }
#pragma unroll
            for (int mt = 0; mt < 2; mt++) {
                int row = wm + (mt << 4) + a_row;
                ldsm4(af[mt], st + SWZ((row << 7) + kb + a_koff));
            }
#pragma unroll
            for (int mt = 0; mt < 2; mt++)
#pragma unroll
                for (int nt = 0; nt < 4; nt++) {
                    mma16816(acc[mt][nt], af[mt], bh[nt]);
                    mma16816(acc[mt][nt], af[mt], bl[nt]);
                }
#pragma unroll
            for (int mt = 0; mt < 2; mt++) {
                int row = wm + (mt << 4) + a_row;
                ldsm4(af[mt], st + 8192 + SWZ((row << 7) + kb + a_koff));
            }
#pragma unroll
            for (int mt = 0; mt < 2; mt++)
#pragma unroll
                for (int nt = 0; nt < 4; nt++)
                    mma16816(acc[mt][nt], af[mt], bh[nt]);
        }
        __syncthreads();
    }

    int g = lane >> 2, t4 = lane & 3;
#pragma unroll
    for (int mt = 0; mt < 2; mt++) {
#pragma unroll
        for (int nt = 0; nt < 4; nt++) {
            int col = n0 + wn + (nt << 3) + (t4 << 1);
            float bx = 0.f, by = 0.f;
            if (bias) { float2 bv = *(const float2*)&bias[col]; bx = bv.x; by = bv.y; }
            int r0 = m0 + wm + (mt << 4) + g;
            *(float2*)&C[((size_t)r0 << 10) + col] =
                make_float2(acc[mt][nt][0] + bx, acc[mt][nt][1] + by);
            *(float2*)&C[((size_t)(r0 + 8) << 10) + col] =
                make_float2(acc[mt][nt][2] + bx, acc[mt][nt][3] + by);
        }
    }
}

// -------- L2 normalize q,k + gates (transposed [b,h,t]); warp per (b,t,h) --------
__global__ __launch_bounds__(256) void qknorm_kernel(const float* __restrict__ q,
                                                     const float* __restrict__ k,
                                                     const float* __restrict__ gqw,
                                                     const float* __restrict__ gkw,
                                                     __nv_bfloat16* __restrict__ qhi,
                                                     __nv_bfloat16* __restrict__ qlo,
                                                     __nv_bfloat16* __restrict__ khi,
                                                     __nv_bfloat16* __restrict__ klo,
                                                     float* __restrict__ gateq,
                                                     float* __restrict__ gatek) {
    int r = blockIdx.x * 8 + (threadIdx.x >> 5);   // (b*T+t)*H + h
    int lane = threadIdx.x & 31;
    int bt = r >> 4, h = r & 15;
    int b = bt >> 11, t = bt & 2047;
    size_t base = ((size_t)bt << 10) + (h << 6) + lane * 2;
    size_t gidx = (((size_t)(b << 4) + h) << 11) + t;

    float2 g1 = *(const float2*)&gqw[lane * 2];
    float2 g2 = *(const float2*)&gkw[lane * 2];

    float2 qv = *(const float2*)&q[base];
    float ss = qv.x * qv.x + qv.y * qv.y;
#pragma unroll
    for (int o = 16; o > 0; o >>= 1) ss += __shfl_xor_sync(0xffffffffu, ss, o);
    float inv = 1.0f / fmaxf(sqrtf(ss), 1e-12f);
    qv.x *= inv; qv.y *= inv;
    __nv_bfloat16 hx, lx, hy, ly;
    split1(qv.x, hx, lx); split1(qv.y, hy, ly);
    *(__nv_bfloat162*)&qhi[base] = __nv_bfloat162(hx, hy);
    *(__nv_bfloat162*)&qlo[base] = __nv_bfloat162(lx, ly);
    float gd = qv.x * g1.x + qv.y * g1.y;
#pragma unroll
    for (int o = 16; o > 0; o >>= 1) gd += __shfl_xor_sync(0xffffffffu, gd, o);
    if (lane == 0) gateq[gidx] = gd;

    float2 kv = *(const float2*)&k[base];
    ss = kv.x * kv.x + kv.y * kv.y;
#pragma unroll
    for (int o = 16; o > 0; o >>= 1) ss += __shfl_xor_sync(0xffffffffu, ss, o);
    inv = 1.0f / fmaxf(sqrtf(ss), 1e-12f);
    kv.x *= inv; kv.y *= inv;
    split1(kv.x, hx, lx); split1(kv.y, hy, ly);
    *(__nv_bfloat162*)&khi[base] = __nv_bfloat162(hx, hy);
    *(__nv_bfloat162*)&klo[base] = __nv_bfloat162(lx, ly);
    gd = kv.x * g2.x + kv.y * g2.y;
#pragma unroll
    for (int o = 16; o > 0; o >>= 1) gd += __shfl_xor_sync(0xffffffffu, gd, o);
    if (lane == 0) gatek[gidx] = gd;
}

// ------------- attention via mma.sync + 2-stage cp.async pipeline (R9) -------------
// Smem: Q hi 0, Q lo 16384; stages at 32768 + s*66048
//   (stage: Khi 0, Klo 16384, Vhi 32768, Vlo 49152, gk 65536..66047); gq at 164864.
#define AT_STG0 32768
#define AT_STGS 66048
#define AT_GQ   164864
#define A_SMEM  165376
__device__ __forceinline__ void at_load_stage(
    uint32_t st, const __nv_bfloat16* khi, const __nv_bfloat16* klo,
    const __nv_bfloat16* vthi, const __nv_bfloat16* vtlo,
    const float* gatek, size_t headoff, size_t vtoff, size_t gkoff,
    int s0, int tid) {
#pragma unroll
    for (int u = tid; u < 2048; u += 256) {   // K hi/lo
        int sp = u >> 10, r = (u >> 3) & 127, c = u & 7;
        const __nv_bfloat16* src = sp ? klo : khi;
        uint32_t dst = st + (sp ? 16384 : 0) + SWZ((r << 7) + (c << 4));
        cpasync16(dst, src + headoff + ((size_t)(s0 + r) << 10) + (c << 3));
    }
#pragma unroll
    for (int u = tid; u < 2048; u += 256) {   // V hi/lo (two 64-s halves)
        int sp = u >> 10, rem = u & 1023;
        int hf = rem >> 9, d = (rem >> 3) & 63, c = rem & 7;
        const __nv_bfloat16* src = sp ? vtlo : vthi;
        uint32_t dst = st + (sp ? 49152 : 32768) + (hf << 13) + SWZ((d << 7) + (c << 4));
        cpasync16(dst, src + vtoff + ((size_t)d << 11) + s0 + (hf << 6) + (c << 3));
    }
    if (tid < 32)
        cpasync16(st + 65536 + (tid << 4), gatek + gkoff + s0 + (tid << 2));
}
__global__ __launch_bounds__(256) void attn_kernel(
    const __nv_bfloat16* __restrict__ qhi, const __nv_bfloat16* __restrict__ qlo,
    const __nv_bfloat16* __restrict__ khi, const __nv_bfloat16* __restrict__ klo,
    const __nv_bfloat16* __restrict__ vthi, const __nv_bfloat16* __restrict__ vtlo,
    const float* __restrict__ gateq, const float* __restrict__ gatek,
    __nv_bfloat16* __restrict__ ohi, __nv_bfloat16* __restrict__ olo) {
    extern __shared__ char smem[];
    uint32_t sb = s2u(smem);
    int tid = threadIdx.x, wid = tid >> 5, lane = tid & 31;
    int g = lane >> 2, t4 = lane & 3;
    int t0 = blockIdx.x << 7;
    int h = blockIdx.y, b = blockIdx.z;
    size_t headoff = (size_t)b * TT * DD + (size_t)h * HDIM;
    size_t vtoff = ((size_t)b * DD + h * HDIM) * TT;
    size_t goff = ((size_t)(b * HH + h)) << 11;

    int a_row = lane & 15;
    int a_koff = (lane >> 4) << 4;
    int b_row = ((lane >> 4) << 3) + (lane & 7);
    int b_koff = ((lane >> 3) & 1) << 4;

    // Q tiles (regular loads) + gq + first K/V stage (cp.async)
    for (int u = tid; u < 2048; u += 256) {
        int sp = u >> 10, r = (u >> 3) & 127, c = u & 7;
        const __nv_bfloat16* src = sp ? qlo : qhi;
        char* dst = smem + (sp ? 16384 : 0);
        *(uint4*)(dst + SWZ((r << 7) + (c << 4))) =
            *(const uint4*)(src + headoff + ((size_t)(t0 + r) << 10) + (c << 3));
    }
    if (tid < 32) {
        float4 gv = *(const float4*)&gateq[goff + t0 + (tid << 2)];
        *(float4*)(smem + AT_GQ + (tid << 4)) = gv;
    }
    at_load_stage(sb + AT_STG0, khi, klo, vthi, vtlo, gatek,
                  headoff, vtoff, goff, 0, tid);
    CP_COMMIT();
    __syncthreads();

    // resident Q fragments (16 t-rows per warp)
    int wm16 = wid << 4;
    uint32_t aQh[4][4], aQl[4][4];
#pragma unroll
    for (int ks = 0; ks < 4; ks++) {
        uint32_t off = SWZ(((wm16 + a_row) << 7) + (ks << 5) + a_koff);
        ldsm4(aQh[ks], sb + off);
        ldsm4(aQl[ks], sb + 16384 + off);
    }
    float gq0 = ((float*)(smem + AT_GQ))[wm16 + g];
    float gq1 = ((float*)(smem + AT_GQ))[wm16 + g + 8];

    float acc[8][4] = {};

    for (int it = 0; it < 16; it++) {
        if (it < 15) {
            at_load_stage(sb + AT_STG0 + ((it + 1) & 1) * AT_STGS, khi, klo, vthi, vtlo,
                          gatek, headoff, vtoff, goff, (it + 1) << 7, tid);
            CP_COMMIT();
            CP_WAIT1();
        } else {
            CP_WAIT0();
        }
        __syncthreads();
        uint32_t stoff = AT_STG0 + (it & 1) * AT_STGS;
        uint32_t st = sb + stoff;

        // S = Q K^T (3-term split)
        float sacc[16][4] = {};
#pragma unroll
        for (int ks = 0; ks < 4; ks++) {
            int kb = ks << 5;
#pragma unroll
            for (int nt2 = 0; nt2 < 8; nt2++) {
                uint32_t off = SWZ((((nt2 << 4) + b_row) << 7) + kb + b_koff);
                uint32_t kh[4], kl[4];
                ldsm4(kh, st + off);
                ldsm4(kl, st + 16384 + off);
                mma16816(sacc[nt2 * 2],     aQh[ks], kh);
                mma16816(sacc[nt2 * 2 + 1], aQh[ks], kh + 2);
                mma16816(sacc[nt2 * 2],     aQh[ks], kl);
                mma16816(sacc[nt2 * 2 + 1], aQh[ks], kl + 2);
                mma16816(sacc[nt2 * 2],     aQl[ks], kh);
                mma16816(sacc[nt2 * 2 + 1], aQl[ks], kh + 2);
            }
        }

        // P = sigmoid((S-th)*sharp)*gq*gk ; pack to bf16 hi/lo A-frags; PV mma
#pragma unroll
        for (int kp = 0; kp < 8; kp++) {
            int ntA = kp * 2, ntB = kp * 2 + 1;
            float2 gkA = *(const float2*)(smem + stoff + 65536 +
                                          (((ntA << 3) + (t4 << 1)) << 2));
            float2 gkB = *(const float2*)(smem + stoff + 65536 +
                                          (((ntB << 3) + (t4 << 1)) << 2));
            float pa0 = sgm(sacc[ntA][0]) * (gq0 * gkA.x);
            float pa1 = sgm(sacc[ntA][1]) * (gq0 * gkA.y);
            float pa2 = sgm(sacc[ntA][2]) * (gq1 * gkA.x);
            float pa3 = sgm(sacc[ntA][3]) * (gq1 * gkA.y);
            float pb0 = sgm(sacc[ntB][0]) * (gq0 * gkB.x);
            float pb1 = sgm(sacc[ntB][1]) * (gq0 * gkB.y);
            float pb2 = sgm(sacc[ntB][2]) * (gq1 * gkB.x);
            float pb3 = sgm(sacc[ntB][3]) * (gq1 * gkB.y);

            uint32_t ph[4], pl[4];
            ph[0] = packbf(pa0, pa1); ph[1] = packbf(pa2, pa3);
            ph[2] = packbf(pb0, pb1); ph[3] = packbf(pb2, pb3);
            {
                float r0 = pa0 - __uint_as_float(ph[0] << 16);
                float r1 = pa1 - __uint_as_float(ph[0] & 0xFFFF0000u);
                pl[0] = packbf(r0, r1);
                r0 = pa2 - __uint_as_float(ph[1] << 16);
                r1 = pa3 - __uint_as_float(ph[1] & 0xFFFF0000u);
                pl[1] = packbf(r0, r1);
                r0 = pb0 - __uint_as_float(ph[2] << 16);
                r1 = pb1 - __uint_as_float(ph[2] & 0xFFFF0000u);
                pl[2] = packbf(r0, r1);
                r0 = pb2 - __uint_as_float(ph[3] << 16);
                r1 = pb3 - __uint_as_float(ph[3] & 0xFFFF0000u);
                pl[3] = packbf(r0, r1);
            }

#pragma unroll
            for (int nt2 = 0; nt2 < 4; nt2++) {
                uint32_t so = SWZ((((nt2 << 4) + b_row) << 7) + ((kp & 3) << 5) + b_koff)
                              + ((kp >> 2) << 13);
                uint32_t vh[4], vl[4];
                ldsm4(vh, st + 32768 + so);
                ldsm4(vl, st + 49152 + so);
                mma16816(acc[nt2 * 2],     ph, vh);
                mma16816(acc[nt2 * 2 + 1], ph, vh + 2);
                mma16816(acc[nt2 * 2],     ph, vl);
                mma16816(acc[nt2 * 2 + 1], ph, vl + 2);
                mma16816(acc[nt2 * 2],     pl, vh);
                mma16816(acc[nt2 * 2 + 1], pl, vh + 2);
            }
        }
        __syncthreads();
    }

    // epilogue: collapse -> bf16 hi/lo splits
#pragma unroll
    for (int nt = 0; nt < 8; nt++) {
        int d0 = (nt << 3) + (t4 << 1);
        int r0 = t0 + wm16 + g;
        __nv_bfloat16 h0, l0, h1, l1;
        split1(acc[nt][0], h0, l0); split1(acc[nt][1], h1, l1);
        size_t i0 = headoff + ((size_t)r0 << 10) + d0;
        *(__nv_bfloat162*)&ohi[i0] = __nv_bfloat162(h0, h1);
        *(__nv_bfloat162*)&olo[i0] = __nv_bfloat162(l0, l1);
        split1(acc[nt][2], h0, l0); split1(acc[nt][3], h1, l1);
        size_t i1 = headoff + ((size_t)(r0 + 8) << 10) + d0;
        *(__nv_bfloat162*)&ohi[i1] = __nv_bfloat162(h0, h1);
        *(__nv_bfloat162*)&olo[i1] = __nv_bfloat162(l0, l1);
    }
}

// -------------------- launch --------------------
extern "C" void kernel_launch(void* const* d_in, const int* in_sizes, int n_in,
                              void* d_out, int out_size) {
    (void)in_sizes; (void)n_in; (void)out_size;
    const float* x   = (const float*)d_in[0];
    const float* Wq  = (const float*)d_in[1];
    const float* Wk  = (const float*)d_in[2];
    const float* Wv  = (const float*)d_in[3];
    const float* gq  = (const float*)d_in[4];
    const float* gk  = (const float*)d_in[5];
    const float* Wo  = (const float*)d_in[6];
    const float* bo  = (const float*)d_in[7];
    const float* lnw = (const float*)d_in[8];
    const float* lnb = (const float*)d_in[9];
    float* out = (float*)d_out;

    float *qb, *kb, *vb, *gqv, *gkv;
    __nv_bfloat16 *xnhi, *xnlo, *xhi, *xlo, *chi, *clo, *wthi, *wtlo;
    __nv_bfloat16 *qhi, *qlo, *khi, *klo, *vthi, *vtlo;
    cudaGetSymbolAddress((void**)&qb,   g_q);
    cudaGetSymbolAddress((void**)&kb,   g_k);
    cudaGetSymbolAddress((void**)&vb,   g_v);
    cudaGetSymbolAddress((void**)&gqv,  g_gq);
    cudaGetSymbolAddress((void**)&gkv,  g_gk);
    cudaGetSymbolAddress((void**)&xnhi, g_xnhi);
    cudaGetSymbolAddress((void**)&xnlo, g_xnlo);
    cudaGetSymbolAddress((void**)&xhi,  g_xhi);
    cudaGetSymbolAddress((void**)&xlo,  g_xlo);
    cudaGetSymbolAddress((void**)&chi,  g_chi);
    cudaGetSymbolAddress((void**)&clo,  g_clo);
    cudaGetSymbolAddress((void**)&qhi,  g_qhi);
    cudaGetSymbolAddress((void**)&qlo,  g_qlo);
    cudaGetSymbolAddress((void**)&khi,  g_khi);
    cudaGetSymbolAddress((void**)&klo,  g_klo);
    cudaGetSymbolAddress((void**)&vthi, g_vthi);
    cudaGetSymbolAddress((void**)&vtlo, g_vtlo);
    cudaGetSymbolAddress((void**)&wthi, g_wthi);
    cudaGetSymbolAddress((void**)&wtlo, g_wtlo);

    const size_t WSZ = (size_t)DD * DD;

    cudaFuncSetAttribute(attn_kernel, cudaFuncAttributeMaxDynamicSharedMemorySize,
                         A_SMEM);
    cudaFuncSetAttribute(tgemm_kernel, cudaFuncAttributeMaxDynamicSharedMemorySize,
                         TG_SMEM);

    dim3 tgrid(DD / 128, MR / 64);        // (8, 64) = 512 CTAs, 2/SM
    dim3 wtgrid(DD / 32, DD / 32, 4);
    dim3 wtblk(32, 8);
    dim3 vtgrid(TT / 32, DD / 32, BB);

    // prep
    ln_kernel<<<MR, 256>>>(x, lnw, lnb, xnhi, xnlo);
    split_kernel<<<(MR * DD) / (256 * 4), 256>>>(x, xhi, xlo);
    wtsplit4_kernel<<<wtgrid, wtblk>>>(Wq, Wk, Wv, Wo, wthi, wtlo);

    // projections on tensor cores
    tgemm_kernel<<<tgrid, 256, TG_SMEM>>>(xnhi, xnlo, wthi + 0 * WSZ, wtlo + 0 * WSZ,
                                          nullptr, qb);
    tgemm_kernel<<<tgrid, 256, TG_SMEM>>>(xnhi, xnlo, wthi + 1 * WSZ, wtlo + 1 * WSZ,
                                          nullptr, kb);
    tgemm_kernel<<<tgrid, 256, TG_SMEM>>>(xhi,  xlo,  wthi + 2 * WSZ, wtlo + 2 * WSZ,
                                          nullptr, vb);

    qknorm_kernel<<<(MR * HH) / 8, 256>>>(qb, kb, gq, gk, qhi, qlo, khi, klo, gqv, gkv);
    vtsplit_kernel<<<vtgrid, wtblk>>>(vb, vthi, vtlo);

    attn_kernel<<<dim3(TT / 128, HH, BB), 256, A_SMEM>>>(
        qhi, qlo, khi, klo, vthi, vtlo, gqv, gkv, chi, clo);

    // output projection + bias
    tgemm_kernel<<<tgrid, 256, TG_SMEM>>>(chi, clo, wthi + 3 * WSZ, wtlo + 3 * WSZ,
                                          bo, out);
}